// round 1
// baseline (speedup 1.0000x reference)
#include <cuda_runtime.h>
#include <math.h>

// ---------------- problem constants ----------------
static const int NTOK   = 8192;   // N
static const int DMODEL = 512;    // D
static const int NHEADS = 8;
static const int DHEAD  = 64;
static const int MLAND  = 256;    // M landmarks
static const int LFOLD  = 32;     // N / M
static const int WPD    = 256;    // weight_params_dim
static const int NEDGE  = 262144; // E
static const int KCONV  = 33;
static const int QKVW   = 3 * NHEADS * DHEAD; // 1536
static const int PITERS = 6;

// ---------------- device scratch (BSS) ----------------
__device__ float g_qkv [NTOK * QKVW];
__device__ float g_ql  [NHEADS * MLAND * DHEAD];
__device__ float g_kl  [NHEADS * MLAND * DHEAD];
__device__ float g_a1  [(long)NHEADS * NTOK * MLAND];
__device__ float g_a2  [NHEADS * MLAND * MLAND];
__device__ float g_a3  [(long)NHEADS * MLAND * NTOK];
__device__ float g_z   [NHEADS * MLAND * MLAND];
__device__ float g_z2  [NHEADS * MLAND * MLAND];
__device__ float g_xz  [NHEADS * MLAND * MLAND];
__device__ float g_t1  [NHEADS * MLAND * MLAND];
__device__ float g_t2  [NHEADS * MLAND * MLAND];
__device__ float g_a3v [NHEADS * MLAND * DHEAD];
__device__ float g_w1  [(long)NHEADS * NTOK * MLAND];
__device__ float g_xh  [NTOK * DMODEL];
__device__ float g_xg  [NTOK * DMODEL];
__device__ float g_enc [NTOK * DMODEL];
__device__ float g_val [NTOK * DMODEL];
__device__ float g_qe  [NTOK * WPD];
__device__ float g_ke  [NTOK * WPD];
__device__ float g_Araw [NTOK];
__device__ float g_alpha[NTOK];
__device__ unsigned int g_norm[2]; // rmax, cmax bits

// ---------------- generic tiled SGEMM ----------------
// C[M,N] = alpha * A[M,K] * op(B);  op(B)=B[N,K]^T if TB else B[K,N]
// batched via strides sA/sB/sC; optional split-K with atomicAdd (C pre-zeroed)
template<bool TB>
__global__ __launch_bounds__(256)
void gemm_k(int M, int N, int K, float alpha,
            const float* __restrict__ A, int lda, long sA,
            const float* __restrict__ B, int ldb, long sB,
            float* __restrict__ C, int ldc, long sC, int kSplit)
{
    int bz = blockIdx.z;
    int batch = bz / kSplit, ks = bz - batch * kSplit;
    A += (long)batch * sA; B += (long)batch * sB; C += (long)batch * sC;
    int chunk = (K + kSplit - 1) / kSplit;
    int k0 = ks * chunk;
    int k1 = min(K, k0 + chunk);

    __shared__ float As[64 * 17];
    __shared__ float Bs[64 * 17];

    int tid = threadIdx.x;
    int row0 = blockIdx.y * 64;
    int col0 = blockIdx.x * 64;
    int tx = tid & 15, ty = tid >> 4;

    float acc[4][4] = {};

    for (int kk = k0; kk < k1; kk += 16) {
        #pragma unroll
        for (int i = 0; i < 4; i++) {
            int e = tid + i * 256;
            int r = e >> 4, c = e & 15;
            int gr = row0 + r, gk = kk + c;
            As[r * 17 + c] = (gr < M && gk < k1) ? A[(long)gr * lda + gk] : 0.f;
        }
        #pragma unroll
        for (int i = 0; i < 4; i++) {
            int e = tid + i * 256;
            if (TB) {
                int n = e >> 4, c = e & 15;
                int gn = col0 + n, gk = kk + c;
                Bs[n * 17 + c] = (gn < N && gk < k1) ? B[(long)gn * ldb + gk] : 0.f;
            } else {
                int c = e >> 6, n = e & 63;
                int gk = kk + c, gn = col0 + n;
                Bs[c * 64 + n] = (gk < k1 && gn < N) ? B[(long)gk * ldb + gn] : 0.f;
            }
        }
        __syncthreads();
        #pragma unroll
        for (int c = 0; c < 16; c++) {
            float a[4], b[4];
            #pragma unroll
            for (int i = 0; i < 4; i++) a[i] = As[(ty * 4 + i) * 17 + c];
            #pragma unroll
            for (int j = 0; j < 4; j++)
                b[j] = TB ? Bs[(tx * 4 + j) * 17 + c] : Bs[c * 64 + tx * 4 + j];
            #pragma unroll
            for (int i = 0; i < 4; i++)
                #pragma unroll
                for (int j = 0; j < 4; j++)
                    acc[i][j] = fmaf(a[i], b[j], acc[i][j]);
        }
        __syncthreads();
    }
    #pragma unroll
    for (int i = 0; i < 4; i++) {
        int gr = row0 + ty * 4 + i; if (gr >= M) continue;
        #pragma unroll
        for (int j = 0; j < 4; j++) {
            int gc = col0 + tx * 4 + j; if (gc >= N) continue;
            float v = alpha * acc[i][j];
            if (kSplit > 1) atomicAdd(&C[(long)gr * ldc + gc], v);
            else C[(long)gr * ldc + gc] = v;
        }
    }
}

static void gemm(bool tb, int M, int N, int K, float alpha,
                 const float* A, int lda, long sA,
                 const float* B, int ldb, long sB,
                 float* C, int ldc, long sC, int batch, int kSplit = 1)
{
    dim3 g((N + 63) / 64, (M + 63) / 64, batch * kSplit);
    if (tb) gemm_k<true ><<<g, 256>>>(M, N, K, alpha, A, lda, sA, B, ldb, sB, C, ldc, sC, kSplit);
    else    gemm_k<false><<<g, 256>>>(M, N, K, alpha, A, lda, sA, B, ldb, sB, C, ldc, sC, kSplit);
}

// ---------------- small kernels ----------------
__global__ void zero_k(float* p, long n) {
    long i = (long)blockIdx.x * blockDim.x + threadIdx.x;
    if (i < n) p[i] = 0.f;
}

__global__ void landmarks_k(const float* __restrict__ qkv,
                            float* __restrict__ ql, float* __restrict__ kl)
{
    int idx = blockIdx.x * blockDim.x + threadIdx.x; // H*M*DH
    if (idx >= NHEADS * MLAND * DHEAD) return;
    int d = idx & 63; int j = (idx >> 6) & 255; int h = idx >> 14;
    const float* qp = qkv + (long)(j * LFOLD) * QKVW + h * DHEAD + d;
    const float* kp = qp + NHEADS * DHEAD; // +512
    float sq = 0.f, sk = 0.f;
    for (int t = 0; t < LFOLD; t++) {
        sq += qp[(long)t * QKVW];
        sk += kp[(long)t * QKVW];
    }
    ql[idx] = sq * (1.f / LFOLD);
    kl[idx] = sk * (1.f / LFOLD);
}

__global__ void softmax_rows_k(float* __restrict__ X, int cols)
{
    long row = blockIdx.x;
    float* x = X + row * (long)cols;
    int tid = threadIdx.x;
    __shared__ float sm[32];
    float m = -1e30f;
    for (int i = tid; i < cols; i += 256) m = fmaxf(m, x[i]);
    for (int o = 16; o; o >>= 1) m = fmaxf(m, __shfl_xor_sync(0xffffffffu, m, o));
    if ((tid & 31) == 0) sm[tid >> 5] = m;
    __syncthreads();
    if (tid == 0) { float bm = sm[0]; for (int w = 1; w < 8; w++) bm = fmaxf(bm, sm[w]); sm[0] = bm; }
    __syncthreads();
    m = sm[0];
    __syncthreads();
    float s = 0.f;
    for (int i = tid; i < cols; i += 256) s += expf(x[i] - m);
    for (int o = 16; o; o >>= 1) s += __shfl_xor_sync(0xffffffffu, s, o);
    if ((tid & 31) == 0) sm[tid >> 5] = s;
    __syncthreads();
    if (tid == 0) { float bs = 0.f; for (int w = 0; w < 8; w++) bs += sm[w]; sm[0] = bs; }
    __syncthreads();
    float inv = 1.f / sm[0];
    for (int i = tid; i < cols; i += 256) x[i] = expf(x[i] - m) * inv;
}

__global__ void a2norm_k(const float* __restrict__ a2, unsigned int* norm)
{
    int h = blockIdx.x; int t = threadIdx.x; // 256 threads
    const float* x = a2 + (long)h * MLAND * MLAND;
    float rs = 0.f, cs = 0.f;
    for (int j = 0; j < MLAND; j++) {
        rs += fabsf(x[t * MLAND + j]);
        cs += fabsf(x[j * MLAND + t]);
    }
    __shared__ float s1[8], s2[8];
    for (int o = 16; o; o >>= 1) {
        rs = fmaxf(rs, __shfl_xor_sync(0xffffffffu, rs, o));
        cs = fmaxf(cs, __shfl_xor_sync(0xffffffffu, cs, o));
    }
    if ((t & 31) == 0) { s1[t >> 5] = rs; s2[t >> 5] = cs; }
    __syncthreads();
    if (t == 0) {
        rs = s1[0]; cs = s2[0];
        for (int w = 1; w < 8; w++) { rs = fmaxf(rs, s1[w]); cs = fmaxf(cs, s2[w]); }
        atomicMax(&norm[0], __float_as_uint(rs));
        atomicMax(&norm[1], __float_as_uint(cs));
    }
}

__global__ void zinit_k(const float* __restrict__ a2, float* __restrict__ z,
                        const unsigned int* __restrict__ norm)
{
    long idx = (long)blockIdx.x * 256 + threadIdx.x;
    if (idx >= (long)NHEADS * MLAND * MLAND) return;
    float inv = 1.f / (__uint_as_float(norm[0]) * __uint_as_float(norm[1]));
    int j = idx & 255; int i = (idx >> 8) & 255; long h = idx >> 16;
    z[idx] = a2[h * 65536 + (long)j * 256 + i] * inv;
}

__global__ void ciminus_k(float* __restrict__ Y, const float* __restrict__ X, float c)
{
    long idx = (long)blockIdx.x * 256 + threadIdx.x;
    if (idx >= (long)NHEADS * MLAND * MLAND) return;
    int j = idx & 255; int i = (idx >> 8) & 255;
    Y[idx] = (i == j ? c : 0.f) - X[idx];
}

__global__ void convadd_k(const float* __restrict__ qkv,
                          const float* __restrict__ rker,
                          float* __restrict__ xh)
{
    long idx = (long)blockIdx.x * 256 + threadIdx.x; // N*512
    if (idx >= (long)NTOK * DMODEL) return;
    int col = idx & 511; long n = idx >> 9;
    int h = col >> 6;
    float s = 0.f;
    #pragma unroll
    for (int t = 0; t < KCONV; t++) {
        long r = n + t - KCONV / 2;
        if (r >= 0 && r < NTOK)
            s += rker[h * KCONV + t] * qkv[r * QKVW + 2 * NHEADS * DHEAD + col];
    }
    xh[idx] += s;
}

__global__ void enc_k(const float* __restrict__ xg, const float* __restrict__ bout,
                      const float* __restrict__ dense, float* __restrict__ enc)
{
    long idx = (long)blockIdx.x * 256 + threadIdx.x;
    if (idx >= (long)NTOK * DMODEL) return;
    int col = idx & 511;
    enc[idx] = xg[idx] + bout[col] + dense[idx];
}

__global__ void edge_k(const float* __restrict__ qe, const float* __restrict__ ke,
                       const int* __restrict__ rows, const int* __restrict__ cols,
                       const float* __restrict__ vals, float* __restrict__ Araw)
{
    int e = blockIdx.x * (blockDim.x >> 5) + (threadIdx.x >> 5);
    int lane = threadIdx.x & 31;
    if (e >= NEDGE) return;
    int r = rows[e], c = cols[e];
    const float4* qr = (const float4*)(qe + (long)r * WPD);
    const float4* kc = (const float4*)(ke + (long)c * WPD);
    float s = 0.f;
    #pragma unroll
    for (int i = lane; i < WPD / 4; i += 32) {
        float4 a = qr[i], b = kc[i];
        s += a.x * b.x + a.y * b.y + a.z * b.z + a.w * b.w;
    }
    for (int o = 16; o; o >>= 1) s += __shfl_xor_sync(0xffffffffu, s, o);
    if (lane == 0) atomicAdd(&Araw[r], s * 0.0625f * vals[e]); // WP^-0.5 = 1/16
}

__global__ void softmax_all_k(const float* __restrict__ A, float* __restrict__ alpha, int n)
{
    __shared__ float sm[32];
    int tid = threadIdx.x; // 1024
    float m = -1e30f;
    for (int i = tid; i < n; i += 1024) m = fmaxf(m, A[i]);
    for (int o = 16; o; o >>= 1) m = fmaxf(m, __shfl_xor_sync(0xffffffffu, m, o));
    if ((tid & 31) == 0) sm[tid >> 5] = m;
    __syncthreads();
    if (tid == 0) { float bm = sm[0]; for (int w = 1; w < 32; w++) bm = fmaxf(bm, sm[w]); sm[0] = bm; }
    __syncthreads();
    m = sm[0];
    __syncthreads();
    float s = 0.f;
    for (int i = tid; i < n; i += 1024) s += expf(A[i] - m);
    for (int o = 16; o; o >>= 1) s += __shfl_xor_sync(0xffffffffu, s, o);
    if ((tid & 31) == 0) sm[tid >> 5] = s;
    __syncthreads();
    if (tid == 0) { float bs = 0.f; for (int w = 0; w < 32; w++) bs += sm[w]; sm[0] = bs; }
    __syncthreads();
    float inv = 1.f / sm[0];
    for (int i = tid; i < n; i += 1024) alpha[i] = expf(A[i] - m) * inv;
}

__global__ void final_k(const float* __restrict__ val, const float* __restrict__ wvb,
                        const float* __restrict__ alpha, const float* __restrict__ enc,
                        const float* __restrict__ Araw, float* __restrict__ out)
{
    long idx = (long)blockIdx.x * 256 + threadIdx.x;
    long total = (long)NTOK * DMODEL;
    if (idx < total) {
        int col = idx & 511; long n = idx >> 9;
        float v = val[idx] + wvb[col];
        float xl = alpha[n] * v;
        float w = 1.f / (1.f + expf(xl)); // sigmoid(-xl)
        float sq = w * w;
        float e = enc[idx];
        out[idx] = xl * 2.f * sq + 2.f * e * (1.f - sq);
    }
    if (idx < NTOK) out[total + idx] = Araw[idx];
}

// ---------------- driver ----------------
extern "C" void kernel_launch(void* const* d_in, const int* in_sizes, int n_in,
                              void* d_out, int out_size)
{
    const float* dense  = (const float*)d_in[0];
    const int*   arows  = (const int*)  d_in[1];
    const int*   acols  = (const int*)  d_in[2];
    const float* avals  = (const float*)d_in[3];
    const float* wq     = (const float*)d_in[4];
    const float* wk     = (const float*)d_in[5];
    const float* w_qkv  = (const float*)d_in[6];
    const float* w_out  = (const float*)d_in[7];
    const float* b_out  = (const float*)d_in[8];
    const float* rker   = (const float*)d_in[9];
    const float* wv_w   = (const float*)d_in[10];
    const float* wv_b   = (const float*)d_in[11];
    float* out = (float*)d_out;

    float *qkv, *ql, *kl, *a1, *a2, *a3, *z, *z2, *xz, *t1, *t2, *a3v, *w1;
    float *xh, *xg, *enc, *val, *qe, *ke, *Araw, *alpha;
    unsigned int* norm;
    cudaGetSymbolAddress((void**)&qkv, g_qkv);
    cudaGetSymbolAddress((void**)&ql,  g_ql);
    cudaGetSymbolAddress((void**)&kl,  g_kl);
    cudaGetSymbolAddress((void**)&a1,  g_a1);
    cudaGetSymbolAddress((void**)&a2,  g_a2);
    cudaGetSymbolAddress((void**)&a3,  g_a3);
    cudaGetSymbolAddress((void**)&z,   g_z);
    cudaGetSymbolAddress((void**)&z2,  g_z2);
    cudaGetSymbolAddress((void**)&xz,  g_xz);
    cudaGetSymbolAddress((void**)&t1,  g_t1);
    cudaGetSymbolAddress((void**)&t2,  g_t2);
    cudaGetSymbolAddress((void**)&a3v, g_a3v);
    cudaGetSymbolAddress((void**)&w1,  g_w1);
    cudaGetSymbolAddress((void**)&xh,  g_xh);
    cudaGetSymbolAddress((void**)&xg,  g_xg);
    cudaGetSymbolAddress((void**)&enc, g_enc);
    cudaGetSymbolAddress((void**)&val, g_val);
    cudaGetSymbolAddress((void**)&qe,  g_qe);
    cudaGetSymbolAddress((void**)&ke,  g_ke);
    cudaGetSymbolAddress((void**)&Araw, g_Araw);
    cudaGetSymbolAddress((void**)&alpha, g_alpha);
    cudaGetSymbolAddress((void**)&norm, g_norm);

    const float qscale = 0.125f; // DIM_HEAD^-0.5

    // 1. qkv = dense @ w_qkv^T  [8192,1536]
    gemm(true, NTOK, QKVW, DMODEL, 1.f, dense, DMODEL, 0, w_qkv, DMODEL, 0,
         qkv, QKVW, 0, 1);

    // 2. landmarks q_l, k_l
    landmarks_k<<<(NHEADS * MLAND * DHEAD + 255) / 256, 256>>>(qkv, ql, kl);

    // 3. a1 logits = scale * q @ k_l^T   [h,8192,256]
    gemm(true, NTOK, MLAND, DHEAD, qscale,
         qkv, QKVW, DHEAD,                 // q head slices
         kl, DHEAD, (long)MLAND * DHEAD,
         a1, MLAND, (long)NTOK * MLAND, NHEADS);
    softmax_rows_k<<<NHEADS * NTOK, 256>>>(a1, MLAND);

    // 4. a2 logits = scale * q_l @ k_l^T [h,256,256]
    gemm(true, MLAND, MLAND, DHEAD, qscale,
         ql, DHEAD, (long)MLAND * DHEAD,
         kl, DHEAD, (long)MLAND * DHEAD,
         a2, MLAND, (long)MLAND * MLAND, NHEADS);
    softmax_rows_k<<<NHEADS * MLAND, 256>>>(a2, MLAND);

    // 5. pinv init
    zero_k<<<1, 32>>>((float*)norm, 2);
    a2norm_k<<<NHEADS, 256>>>(a2, norm);
    {
        long n = (long)NHEADS * MLAND * MLAND;
        zinit_k<<<(int)((n + 255) / 256), 256>>>(a2, z, norm);
    }

    // 6. pinv iterations
    float* zin = z; float* zout = z2;
    long smm = (long)MLAND * MLAND;
    int mmblocks = (int)((NHEADS * smm + 255) / 256);
    for (int it = 0; it < PITERS; it++) {
        gemm(false, MLAND, MLAND, MLAND, 1.f, a2, MLAND, smm, zin, MLAND, smm,
             xz, MLAND, smm, NHEADS);                               // xz = x @ z
        ciminus_k<<<mmblocks, 256>>>(t1, xz, 7.f);                  // t1 = 7I - xz
        gemm(false, MLAND, MLAND, MLAND, 1.f, xz, MLAND, smm, t1, MLAND, smm,
             t2, MLAND, smm, NHEADS);                               // t2 = xz @ t1
        ciminus_k<<<mmblocks, 256>>>(t2, t2, 15.f);                 // t2 = 15I - t2
        gemm(false, MLAND, MLAND, MLAND, 1.f, xz, MLAND, smm, t2, MLAND, smm,
             t1, MLAND, smm, NHEADS);                               // t1 = xz @ t2
        ciminus_k<<<mmblocks, 256>>>(t1, t1, 13.f);                 // t1 = 13I - t1
        gemm(false, MLAND, MLAND, MLAND, 0.25f, zin, MLAND, smm, t1, MLAND, smm,
             zout, MLAND, smm, NHEADS);                             // z = 0.25 z @ t1
        float* tmp = zin; zin = zout; zout = tmp;
    }
    float* zfin = zin;

    // 7. a3 logits = scale * q_l @ k^T  [h,256,8192]
    gemm(true, MLAND, NTOK, DHEAD, qscale,
         ql, DHEAD, (long)MLAND * DHEAD,
         qkv + NHEADS * DHEAD, QKVW, DHEAD,
         a3, NTOK, (long)MLAND * NTOK, NHEADS);
    softmax_rows_k<<<NHEADS * MLAND, 256>>>(a3, NTOK);

    // 8. a3v = a3 @ v  [h,256,64]  (split-K)
    zero_k<<<(NHEADS * MLAND * DHEAD + 255) / 256, 256>>>(a3v, NHEADS * MLAND * DHEAD);
    gemm(false, MLAND, DHEAD, NTOK, 1.f,
         a3, NTOK, (long)MLAND * NTOK,
         qkv + 2 * NHEADS * DHEAD, QKVW, DHEAD,
         a3v, DHEAD, (long)MLAND * DHEAD, NHEADS, 16);

    // 9. w1 = a1 @ zfin  [h,8192,256]
    gemm(false, NTOK, MLAND, MLAND, 1.f,
         a1, MLAND, (long)NTOK * MLAND,
         zfin, MLAND, smm,
         w1, MLAND, (long)NTOK * MLAND, NHEADS);

    // 10. outh = w1 @ a3v  -> written into xh[n, h*64+d]
    gemm(false, NTOK, DHEAD, MLAND, 1.f,
         w1, MLAND, (long)NTOK * MLAND,
         a3v, DHEAD, (long)MLAND * DHEAD,
         xh, DMODEL, DHEAD, NHEADS);

    // 11. residual depthwise conv on v, added into xh
    convadd_k<<<(int)(((long)NTOK * DMODEL + 255) / 256), 256>>>(qkv, rker, xh);

    // 12. xg = xh @ w_out^T ; enc = xg + b_out + dense
    gemm(true, NTOK, DMODEL, DMODEL, 1.f, xh, DMODEL, 0, w_out, DMODEL, 0,
         xg, DMODEL, 0, 1);
    enc_k<<<(int)(((long)NTOK * DMODEL + 255) / 256), 256>>>(xg, b_out, dense, enc);

    // 13. qe = enc @ wq ; ke = enc @ wk
    gemm(false, NTOK, WPD, DMODEL, 1.f, enc, DMODEL, 0, wq, WPD, 0, qe, WPD, 0, 1);
    gemm(false, NTOK, WPD, DMODEL, 1.f, enc, DMODEL, 0, wk, WPD, 0, ke, WPD, 0, 1);

    // 14. edge scores -> segment sum
    zero_k<<<(NTOK + 255) / 256, 256>>>(Araw, NTOK);
    edge_k<<<(NEDGE + 7) / 8, 256>>>(qe, ke, arows, acols, avals, Araw);

    // 15. alpha = softmax(A_raw) over all N
    softmax_all_k<<<1, 1024>>>(Araw, alpha, NTOK);

    // 16. value = dense @ wv_w^T
    gemm(true, NTOK, DMODEL, DMODEL, 1.f, dense, DMODEL, 0, wv_w, DMODEL, 0,
         val, DMODEL, 0, 1);

    // 17. final gated blend + A_raw copy
    final_k<<<(int)(((long)NTOK * DMODEL + 255) / 256), 256>>>(val, wv_b, alpha, enc, Araw, out);
}

// round 2
// speedup vs baseline: 1.3628x; 1.3628x over previous
#include <cuda_runtime.h>
#include <math.h>

// ---------------- problem constants ----------------
static const int NTOK   = 8192;   // N
static const int DMODEL = 512;    // D
static const int NHEADS = 8;
static const int DHEAD  = 64;
static const int MLAND  = 256;    // M landmarks
static const int LFOLD  = 32;     // N / M
static const int WPD    = 256;    // weight_params_dim
static const int NEDGE  = 262144; // E
static const int KCONV  = 33;
static const int QKVW   = 3 * NHEADS * DHEAD; // 1536
static const int PITERS = 6;

// ---------------- device scratch (BSS) ----------------
__device__ float g_qkv [NTOK * QKVW];
__device__ float g_ql  [NHEADS * MLAND * DHEAD];
__device__ float g_kl  [NHEADS * MLAND * DHEAD];
__device__ float g_a1  [(long)NHEADS * NTOK * MLAND];
__device__ float g_a2  [NHEADS * MLAND * MLAND];
__device__ float g_a3  [(long)NHEADS * MLAND * NTOK];
__device__ float g_z   [NHEADS * MLAND * MLAND];
__device__ float g_z2  [NHEADS * MLAND * MLAND];
__device__ float g_xz  [NHEADS * MLAND * MLAND];
__device__ float g_t1  [NHEADS * MLAND * MLAND];
__device__ float g_t2  [NHEADS * MLAND * MLAND];
__device__ float g_a3v [NHEADS * MLAND * DHEAD];
__device__ float g_w1  [(long)NHEADS * NTOK * MLAND];
__device__ float g_xh  [NTOK * DMODEL];
__device__ float g_xg  [NTOK * DMODEL];
__device__ float g_enc [NTOK * DMODEL];
__device__ float g_val [NTOK * DMODEL];
__device__ float g_qe  [NTOK * WPD];
__device__ float g_ke  [NTOK * WPD];
__device__ float g_Araw [NTOK];
__device__ float g_alpha[NTOK];
__device__ unsigned int g_norm[2];

// =====================================================================
// gemm128: C[M,N] = alpha * A[M,K] @ op(B).  Block tile 128x128, BK=8,
// 256 threads, 8x8 per thread, conflict-free lane mapping.
// REQUIRES: M%128==0, N%128==0, K%8==0, all lds %4==0, 16B-aligned ptrs.
// TB: B is [N,K] row-major (B^T applied). !TB: B is [K,N].
// =====================================================================
template<bool TB>
__global__ __launch_bounds__(256, 2)
void gemm128_k(int M, int N, int K, float alpha,
               const float* __restrict__ A, int lda, long sA,
               const float* __restrict__ B, int ldb, long sB,
               float* __restrict__ C, int ldc, long sC)
{
    A += (long)blockIdx.z * sA;
    B += (long)blockIdx.z * sB;
    C += (long)blockIdx.z * sC;
    const int row0 = blockIdx.y * 128;
    const int col0 = blockIdx.x * 128;

    __shared__ float As[8][128];
    __shared__ float Bs[8][128];

    const int tid  = threadIdx.x;
    const int lane = tid & 31;
    const int w    = tid >> 5;
    const int tx   = lane & 7;       // 8 distinct -> banks 0..31 for B reads
    const int ty   = lane >> 3;      // 0..3
    const int wr   = w & 3;          // 4 row groups of 32
    const int wc   = w >> 2;         // 2 col groups of 64

    const int ar = tid >> 1;         // 0..127
    const int ak = (tid & 1) * 4;    // 0 or 4
    const int bk = tid >> 5;         // 0..7  (NT load)
    const int bn = (tid & 31) * 4;   // 0..124 (NT load)

    const int rbase = wr * 32 + ty * 4;
    const int cbase = wc * 64 + tx * 4;

    float acc[8][8];
    #pragma unroll
    for (int i = 0; i < 8; i++)
        #pragma unroll
        for (int j = 0; j < 8; j++) acc[i][j] = 0.f;

    const float* Ap = A + (long)(row0 + ar) * lda + ak;
    const float* Bp = TB ? (B + (long)(col0 + ar) * ldb + ak)
                         : (B + (long)bk * ldb + col0 + bn);

    for (int k0 = 0; k0 < K; k0 += 8) {
        float4 av = *(const float4*)(Ap + k0);
        float4 bv = TB ? *(const float4*)(Bp + k0)
                       : *(const float4*)(Bp + (long)k0 * ldb);
        As[ak + 0][ar] = av.x; As[ak + 1][ar] = av.y;
        As[ak + 2][ar] = av.z; As[ak + 3][ar] = av.w;
        if (TB) {
            Bs[ak + 0][ar] = bv.x; Bs[ak + 1][ar] = bv.y;
            Bs[ak + 2][ar] = bv.z; Bs[ak + 3][ar] = bv.w;
        } else {
            *(float4*)&Bs[bk][bn] = bv;
        }
        __syncthreads();
        #pragma unroll
        for (int k = 0; k < 8; k++) {
            float a[8], b[8];
            *(float4*)(a)     = *(const float4*)&As[k][rbase];
            *(float4*)(a + 4) = *(const float4*)&As[k][rbase + 16];
            *(float4*)(b)     = *(const float4*)&Bs[k][cbase];
            *(float4*)(b + 4) = *(const float4*)&Bs[k][cbase + 32];
            #pragma unroll
            for (int i = 0; i < 8; i++)
                #pragma unroll
                for (int j = 0; j < 8; j++)
                    acc[i][j] = fmaf(a[i], b[j], acc[i][j]);
        }
        __syncthreads();
    }

    #pragma unroll
    for (int i = 0; i < 8; i++) {
        int gr = row0 + rbase + ((i < 4) ? i : 12 + i); // i>=4 -> +16+(i-4)
        float* Cr = C + (long)gr * ldc + col0;
        float4 v0 = make_float4(alpha * acc[i][0], alpha * acc[i][1],
                                alpha * acc[i][2], alpha * acc[i][3]);
        float4 v1 = make_float4(alpha * acc[i][4], alpha * acc[i][5],
                                alpha * acc[i][6], alpha * acc[i][7]);
        *(float4*)(Cr + cbase)      = v0;
        *(float4*)(Cr + cbase + 32) = v1;
    }
}

static void gemm128(bool tb, int M, int N, int K, float alpha,
                    const float* A, int lda, long sA,
                    const float* B, int ldb, long sB,
                    float* C, int ldc, long sC, int batch)
{
    dim3 g(N / 128, M / 128, batch);
    if (tb) gemm128_k<true ><<<g, 256>>>(M, N, K, alpha, A, lda, sA, B, ldb, sB, C, ldc, sC);
    else    gemm128_k<false><<<g, 256>>>(M, N, K, alpha, A, lda, sA, B, ldb, sB, C, ldc, sC);
}

// =====================================================================
// gemm12864: 128x64 block tile for N=64 GEMMs. NT only (B is [K,N]).
// 256 threads, 4x8 per thread. Optional split-K with atomicAdd.
// REQUIRES: M%128==0, N%64==0, (K/kSplit)%8==0.
// =====================================================================
__global__ __launch_bounds__(256, 2)
void gemm12864_k(int M, int N, int K, float alpha,
                 const float* __restrict__ A, int lda, long sA,
                 const float* __restrict__ B, int ldb, long sB,
                 float* __restrict__ C, int ldc, long sC, int kSplit)
{
    int bz = blockIdx.z;
    int batch = bz / kSplit, ks = bz - batch * kSplit;
    A += (long)batch * sA;
    B += (long)batch * sB;
    C += (long)batch * sC;
    int chunk = K / kSplit;
    int k0s = ks * chunk, k1 = k0s + chunk;

    const int row0 = blockIdx.y * 128;
    const int col0 = blockIdx.x * 64;

    __shared__ float As[8][128];
    __shared__ float Bs[8][64];

    const int tid  = threadIdx.x;
    const int lane = tid & 31;
    const int w    = tid >> 5;       // 0..7 (row groups of 16)
    const int tx   = lane & 7;
    const int ty   = lane >> 3;

    const int ar = tid >> 1;
    const int ak = (tid & 1) * 4;
    const int bkk = tid >> 4;        // 0..7 for tid<128
    const int bnn = (tid & 15) * 4;  // 0..60

    const int rbase = w * 16 + ty * 4;
    const int cbase = tx * 4;

    float acc[4][8];
    #pragma unroll
    for (int i = 0; i < 4; i++)
        #pragma unroll
        for (int j = 0; j < 8; j++) acc[i][j] = 0.f;

    const float* Ap = A + (long)(row0 + ar) * lda + ak;
    const float* Bp = B + (long)bkk * ldb + col0 + bnn;

    for (int k0 = k0s; k0 < k1; k0 += 8) {
        float4 av = *(const float4*)(Ap + k0);
        float4 bv;
        if (tid < 128) bv = *(const float4*)(Bp + (long)k0 * ldb);
        As[ak + 0][ar] = av.x; As[ak + 1][ar] = av.y;
        As[ak + 2][ar] = av.z; As[ak + 3][ar] = av.w;
        if (tid < 128) *(float4*)&Bs[bkk][bnn] = bv;
        __syncthreads();
        #pragma unroll
        for (int k = 0; k < 8; k++) {
            float a[4], b[8];
            *(float4*)(a)     = *(const float4*)&As[k][rbase];
            *(float4*)(b)     = *(const float4*)&Bs[k][cbase];
            *(float4*)(b + 4) = *(const float4*)&Bs[k][cbase + 32];
            #pragma unroll
            for (int i = 0; i < 4; i++)
                #pragma unroll
                for (int j = 0; j < 8; j++)
                    acc[i][j] = fmaf(a[i], b[j], acc[i][j]);
        }
        __syncthreads();
    }

    #pragma unroll
    for (int i = 0; i < 4; i++) {
        int gr = row0 + rbase + i;
        float* Cr = C + (long)gr * ldc + col0;
        if (kSplit > 1) {
            #pragma unroll
            for (int j = 0; j < 4; j++) atomicAdd(Cr + cbase + j, alpha * acc[i][j]);
            #pragma unroll
            for (int j = 4; j < 8; j++) atomicAdd(Cr + cbase + 28 + j, alpha * acc[i][j]);
        } else {
            float4 v0 = make_float4(alpha * acc[i][0], alpha * acc[i][1],
                                    alpha * acc[i][2], alpha * acc[i][3]);
            float4 v1 = make_float4(alpha * acc[i][4], alpha * acc[i][5],
                                    alpha * acc[i][6], alpha * acc[i][7]);
            *(float4*)(Cr + cbase)      = v0;
            *(float4*)(Cr + cbase + 32) = v1;
        }
    }
}

// =====================================================================
// gemm64ep: specialized 256x256x256 batched GEMM (pinv), NT, 64x64 tile,
// fused epilogue:  C = alpha*(A@B) + diag*I,  optional C2 likewise.
// =====================================================================
__global__ __launch_bounds__(256)
void gemm64ep_k(float alpha, float diag,
                const float* __restrict__ A, const float* __restrict__ B,
                float* __restrict__ C,
                float alpha2, float diag2, float* __restrict__ C2)
{
    const long sb = (long)MLAND * MLAND;
    A  += blockIdx.z * sb;
    B  += blockIdx.z * sb;
    C  += blockIdx.z * sb;
    if (C2) C2 += blockIdx.z * sb;

    __shared__ float As[64 * 17];
    __shared__ float Bs[16 * 64];

    int tid = threadIdx.x;
    int row0 = blockIdx.y * 64;
    int col0 = blockIdx.x * 64;
    int tx = tid & 15, ty = tid >> 4;

    float acc[4][4] = {};

    for (int kk = 0; kk < 256; kk += 16) {
        #pragma unroll
        for (int i = 0; i < 4; i++) {
            int e = tid + i * 256;
            int r = e >> 4, c = e & 15;
            As[r * 17 + c] = A[(long)(row0 + r) * 256 + kk + c];
        }
        #pragma unroll
        for (int i = 0; i < 4; i++) {
            int e = tid + i * 256;
            int c = e >> 6, n = e & 63;
            Bs[c * 64 + n] = B[(long)(kk + c) * 256 + col0 + n];
        }
        __syncthreads();
        #pragma unroll
        for (int c = 0; c < 16; c++) {
            float a[4], b[4];
            #pragma unroll
            for (int i = 0; i < 4; i++) a[i] = As[(ty * 4 + i) * 17 + c];
            #pragma unroll
            for (int j = 0; j < 4; j++) b[j] = Bs[c * 64 + tx * 4 + j];
            #pragma unroll
            for (int i = 0; i < 4; i++)
                #pragma unroll
                for (int j = 0; j < 4; j++)
                    acc[i][j] = fmaf(a[i], b[j], acc[i][j]);
        }
        __syncthreads();
    }
    #pragma unroll
    for (int i = 0; i < 4; i++) {
        int gr = row0 + ty * 4 + i;
        #pragma unroll
        for (int j = 0; j < 4; j++) {
            int gc = col0 + tx * 4 + j;
            float d = (gr == gc) ? 1.f : 0.f;
            C[(long)gr * 256 + gc] = alpha * acc[i][j] + diag * d;
            if (C2) C2[(long)gr * 256 + gc] = alpha2 * acc[i][j] + diag2 * d;
        }
    }
}

// ---------------- small kernels ----------------
__global__ void zeros_k(float* a3v, float* Araw, unsigned int* norm)
{
    long i = (long)blockIdx.x * 256 + threadIdx.x;
    if (i < NHEADS * MLAND * DHEAD) a3v[i] = 0.f;
    if (i < NTOK) Araw[i] = 0.f;
    if (i < 2) norm[i] = 0u;
}

__global__ void landmarks_k(const float* __restrict__ qkv,
                            float* __restrict__ ql, float* __restrict__ kl)
{
    int idx = blockIdx.x * blockDim.x + threadIdx.x;
    if (idx >= NHEADS * MLAND * DHEAD) return;
    int d = idx & 63; int j = (idx >> 6) & 255; int h = idx >> 14;
    const float* qp = qkv + (long)(j * LFOLD) * QKVW + h * DHEAD + d;
    const float* kp = qp + NHEADS * DHEAD;
    float sq = 0.f, sk = 0.f;
    #pragma unroll 4
    for (int t = 0; t < LFOLD; t++) {
        sq += qp[(long)t * QKVW];
        sk += kp[(long)t * QKVW];
    }
    ql[idx] = sq * (1.f / LFOLD);
    kl[idx] = sk * (1.f / LFOLD);
}

// one row of 256 per block, value held in register (single pass)
__global__ __launch_bounds__(256)
void softmax256_k(float* __restrict__ X)
{
    float* x = X + (long)blockIdx.x * 256;
    int tid = threadIdx.x;
    __shared__ float sm[8];
    float v = x[tid];
    float m = v;
    #pragma unroll
    for (int o = 16; o; o >>= 1) m = fmaxf(m, __shfl_xor_sync(0xffffffffu, m, o));
    if ((tid & 31) == 0) sm[tid >> 5] = m;
    __syncthreads();
    m = sm[0];
    #pragma unroll
    for (int i = 1; i < 8; i++) m = fmaxf(m, sm[i]);
    float e = __expf(v - m);
    float s = e;
    #pragma unroll
    for (int o = 16; o; o >>= 1) s += __shfl_xor_sync(0xffffffffu, s, o);
    __syncthreads();
    if ((tid & 31) == 0) sm[tid >> 5] = s;
    __syncthreads();
    s = sm[0];
    #pragma unroll
    for (int i = 1; i < 8; i++) s += sm[i];
    x[tid] = e * (1.f / s);
}

// one row of 8192 per block, 1024 threads, 8 values/thread in registers
__global__ __launch_bounds__(1024)
void softmax8192_k(float* __restrict__ X)
{
    float* x = X + (long)blockIdx.x * 8192;
    int tid = threadIdx.x;
    __shared__ float sm[32];
    float4 v0 = *(const float4*)(x + tid * 8);
    float4 v1 = *(const float4*)(x + tid * 8 + 4);
    float m = fmaxf(fmaxf(fmaxf(v0.x, v0.y), fmaxf(v0.z, v0.w)),
                    fmaxf(fmaxf(v1.x, v1.y), fmaxf(v1.z, v1.w)));
    #pragma unroll
    for (int o = 16; o; o >>= 1) m = fmaxf(m, __shfl_xor_sync(0xffffffffu, m, o));
    if ((tid & 31) == 0) sm[tid >> 5] = m;
    __syncthreads();
    m = sm[0];
    #pragma unroll
    for (int i = 1; i < 32; i++) m = fmaxf(m, sm[i]);
    float e0 = __expf(v0.x - m), e1 = __expf(v0.y - m);
    float e2 = __expf(v0.z - m), e3 = __expf(v0.w - m);
    float e4 = __expf(v1.x - m), e5 = __expf(v1.y - m);
    float e6 = __expf(v1.z - m), e7 = __expf(v1.w - m);
    float s = ((e0 + e1) + (e2 + e3)) + ((e4 + e5) + (e6 + e7));
    #pragma unroll
    for (int o = 16; o; o >>= 1) s += __shfl_xor_sync(0xffffffffu, s, o);
    __syncthreads();
    if ((tid & 31) == 0) sm[tid >> 5] = s;
    __syncthreads();
    s = sm[0];
    #pragma unroll
    for (int i = 1; i < 32; i++) s += sm[i];
    float inv = 1.f / s;
    *(float4*)(x + tid * 8)     = make_float4(e0 * inv, e1 * inv, e2 * inv, e3 * inv);
    *(float4*)(x + tid * 8 + 4) = make_float4(e4 * inv, e5 * inv, e6 * inv, e7 * inv);
}

__global__ void a2norm_k(const float* __restrict__ a2, unsigned int* norm)
{
    int h = blockIdx.x; int t = threadIdx.x;
    const float* x = a2 + (long)h * MLAND * MLAND;
    float rs = 0.f, cs = 0.f;
    for (int j = 0; j < MLAND; j++) {
        rs += fabsf(x[t * MLAND + j]);
        cs += fabsf(x[j * MLAND + t]);
    }
    __shared__ float s1[8], s2[8];
    for (int o = 16; o; o >>= 1) {
        rs = fmaxf(rs, __shfl_xor_sync(0xffffffffu, rs, o));
        cs = fmaxf(cs, __shfl_xor_sync(0xffffffffu, cs, o));
    }
    if ((t & 31) == 0) { s1[t >> 5] = rs; s2[t >> 5] = cs; }
    __syncthreads();
    if (t == 0) {
        rs = s1[0]; cs = s2[0];
        for (int w = 1; w < 8; w++) { rs = fmaxf(rs, s1[w]); cs = fmaxf(cs, s2[w]); }
        atomicMax(&norm[0], __float_as_uint(rs));
        atomicMax(&norm[1], __float_as_uint(cs));
    }
}

__global__ void zinit_k(const float* __restrict__ a2, float* __restrict__ z,
                        const unsigned int* __restrict__ norm)
{
    long idx = (long)blockIdx.x * 256 + threadIdx.x;
    if (idx >= (long)NHEADS * MLAND * MLAND) return;
    float inv = 1.f / (__uint_as_float(norm[0]) * __uint_as_float(norm[1]));
    int j = idx & 255; int i = (idx >> 8) & 255; long h = idx >> 16;
    z[idx] = a2[h * 65536 + (long)j * 256 + i] * inv;
}

__global__ void convadd_k(const float* __restrict__ qkv,
                          const float* __restrict__ rker,
                          float* __restrict__ xh)
{
    long idx = (long)blockIdx.x * 256 + threadIdx.x;
    if (idx >= (long)NTOK * DMODEL) return;
    int col = idx & 511; long n = idx >> 9;
    int h = col >> 6;
    float s = 0.f;
    #pragma unroll
    for (int t = 0; t < KCONV; t++) {
        long r = n + t - KCONV / 2;
        if (r >= 0 && r < NTOK)
            s += rker[h * KCONV + t] * qkv[r * QKVW + 2 * NHEADS * DHEAD + col];
    }
    xh[idx] += s;
}

__global__ void enc_k(const float* __restrict__ xg, const float* __restrict__ bout,
                      const float* __restrict__ dense, float* __restrict__ enc)
{
    long idx = (long)blockIdx.x * 256 + threadIdx.x;
    if (idx >= (long)NTOK * DMODEL) return;
    int col = idx & 511;
    enc[idx] = xg[idx] + bout[col] + dense[idx];
}

__global__ void edge_k(const float* __restrict__ qe, const float* __restrict__ ke,
                       const int* __restrict__ rows, const int* __restrict__ cols,
                       const float* __restrict__ vals, float* __restrict__ Araw)
{
    int e = blockIdx.x * (blockDim.x >> 5) + (threadIdx.x >> 5);
    int lane = threadIdx.x & 31;
    if (e >= NEDGE) return;
    int r = rows[e], c = cols[e];
    const float4* qr = (const float4*)(qe + (long)r * WPD);
    const float4* kc = (const float4*)(ke + (long)c * WPD);
    float s = 0.f;
    #pragma unroll
    for (int i = lane; i < WPD / 4; i += 32) {
        float4 a = qr[i], b = kc[i];
        s += a.x * b.x + a.y * b.y + a.z * b.z + a.w * b.w;
    }
    for (int o = 16; o; o >>= 1) s += __shfl_xor_sync(0xffffffffu, s, o);
    if (lane == 0) atomicAdd(&Araw[r], s * 0.0625f * vals[e]);
}

__global__ void softmax_all_k(const float* __restrict__ A, float* __restrict__ alpha, int n)
{
    __shared__ float sm[32];
    int tid = threadIdx.x; // 1024
    float m = -1e30f;
    for (int i = tid; i < n; i += 1024) m = fmaxf(m, A[i]);
    for (int o = 16; o; o >>= 1) m = fmaxf(m, __shfl_xor_sync(0xffffffffu, m, o));
    if ((tid & 31) == 0) sm[tid >> 5] = m;
    __syncthreads();
    if (tid == 0) { float bm = sm[0]; for (int w = 1; w < 32; w++) bm = fmaxf(bm, sm[w]); sm[0] = bm; }
    __syncthreads();
    m = sm[0];
    __syncthreads();
    float s = 0.f;
    for (int i = tid; i < n; i += 1024) s += __expf(A[i] - m);
    for (int o = 16; o; o >>= 1) s += __shfl_xor_sync(0xffffffffu, s, o);
    if ((tid & 31) == 0) sm[tid >> 5] = s;
    __syncthreads();
    if (tid == 0) { float bs = 0.f; for (int w = 0; w < 32; w++) bs += sm[w]; sm[0] = bs; }
    __syncthreads();
    float inv = 1.f / sm[0];
    for (int i = tid; i < n; i += 1024) alpha[i] = __expf(A[i] - m) * inv;
}

__global__ void final_k(const float* __restrict__ val, const float* __restrict__ wvb,
                        const float* __restrict__ alpha, const float* __restrict__ enc,
                        const float* __restrict__ Araw, float* __restrict__ out)
{
    long idx = (long)blockIdx.x * 256 + threadIdx.x;
    long total = (long)NTOK * DMODEL;
    if (idx < total) {
        int col = idx & 511; long n = idx >> 9;
        float v = val[idx] + wvb[col];
        float xl = alpha[n] * v;
        float w = 1.f / (1.f + __expf(xl)); // sigmoid(-xl)
        float sq = w * w;
        float e = enc[idx];
        out[idx] = xl * 2.f * sq + 2.f * e * (1.f - sq);
    }
    if (idx < NTOK) out[total + idx] = Araw[idx];
}

// ---------------- driver ----------------
extern "C" void kernel_launch(void* const* d_in, const int* in_sizes, int n_in,
                              void* d_out, int out_size)
{
    const float* dense  = (const float*)d_in[0];
    const int*   arows  = (const int*)  d_in[1];
    const int*   acols  = (const int*)  d_in[2];
    const float* avals  = (const float*)d_in[3];
    const float* wq     = (const float*)d_in[4];
    const float* wk     = (const float*)d_in[5];
    const float* w_qkv  = (const float*)d_in[6];
    const float* w_out  = (const float*)d_in[7];
    const float* b_out  = (const float*)d_in[8];
    const float* rker   = (const float*)d_in[9];
    const float* wv_w   = (const float*)d_in[10];
    const float* wv_b   = (const float*)d_in[11];
    float* out = (float*)d_out;

    float *qkv, *ql, *kl, *a1, *a2, *a3, *z, *z2, *xz, *t1, *t2, *a3v, *w1;
    float *xh, *xg, *enc, *val, *qe, *ke, *Araw, *alpha;
    unsigned int* norm;
    cudaGetSymbolAddress((void**)&qkv, g_qkv);
    cudaGetSymbolAddress((void**)&ql,  g_ql);
    cudaGetSymbolAddress((void**)&kl,  g_kl);
    cudaGetSymbolAddress((void**)&a1,  g_a1);
    cudaGetSymbolAddress((void**)&a2,  g_a2);
    cudaGetSymbolAddress((void**)&a3,  g_a3);
    cudaGetSymbolAddress((void**)&z,   g_z);
    cudaGetSymbolAddress((void**)&z2,  g_z2);
    cudaGetSymbolAddress((void**)&xz,  g_xz);
    cudaGetSymbolAddress((void**)&t1,  g_t1);
    cudaGetSymbolAddress((void**)&t2,  g_t2);
    cudaGetSymbolAddress((void**)&a3v, g_a3v);
    cudaGetSymbolAddress((void**)&w1,  g_w1);
    cudaGetSymbolAddress((void**)&xh,  g_xh);
    cudaGetSymbolAddress((void**)&xg,  g_xg);
    cudaGetSymbolAddress((void**)&enc, g_enc);
    cudaGetSymbolAddress((void**)&val, g_val);
    cudaGetSymbolAddress((void**)&qe,  g_qe);
    cudaGetSymbolAddress((void**)&ke,  g_ke);
    cudaGetSymbolAddress((void**)&Araw, g_Araw);
    cudaGetSymbolAddress((void**)&alpha, g_alpha);
    cudaGetSymbolAddress((void**)&norm, g_norm);

    const float qscale = 0.125f; // DIM_HEAD^-0.5
    const long  smm    = (long)MLAND * MLAND;

    // 0. zero scratch (a3v accum, Araw accum, norm)
    zeros_k<<<(NHEADS * MLAND * DHEAD + 255) / 256, 256>>>(a3v, Araw, norm);

    // 1. qkv = dense @ w_qkv^T  [8192,1536]
    gemm128(true, NTOK, QKVW, DMODEL, 1.f, dense, DMODEL, 0, w_qkv, DMODEL, 0,
            qkv, QKVW, 0, 1);

    // 2. landmarks
    landmarks_k<<<(NHEADS * MLAND * DHEAD + 255) / 256, 256>>>(qkv, ql, kl);

    // 3. a1 = softmax(scale * q @ k_l^T)   [h,8192,256]
    gemm128(true, NTOK, MLAND, DHEAD, qscale,
            qkv, QKVW, DHEAD, kl, DHEAD, (long)MLAND * DHEAD,
            a1, MLAND, (long)NTOK * MLAND, NHEADS);
    softmax256_k<<<NHEADS * NTOK, 256>>>(a1);

    // 4. a2 = softmax(scale * q_l @ k_l^T) [h,256,256]
    gemm128(true, MLAND, MLAND, DHEAD, qscale,
            ql, DHEAD, (long)MLAND * DHEAD, kl, DHEAD, (long)MLAND * DHEAD,
            a2, MLAND, smm, NHEADS);
    softmax256_k<<<NHEADS * MLAND, 256>>>(a2);

    // 5. pinv init
    a2norm_k<<<NHEADS, 256>>>(a2, norm);
    zinit_k<<<(int)((NHEADS * smm + 255) / 256), 256>>>(a2, z, norm);

    // 6. pinv iterations (fused epilogues, 4 GEMMs/iter)
    float* zin = z; float* zout = z2;
    dim3 gp(4, 4, NHEADS);
    for (int it = 0; it < PITERS; it++) {
        // xz = a2@zin ; t1 = 7I - xz
        gemm64ep_k<<<gp, 256>>>(1.f, 0.f, a2, zin, xz, -1.f, 7.f, t1);
        // t2 = 15I - xz@t1
        gemm64ep_k<<<gp, 256>>>(-1.f, 15.f, xz, t1, t2, 0.f, 0.f, nullptr);
        // t1 = 13I - xz@t2
        gemm64ep_k<<<gp, 256>>>(-1.f, 13.f, xz, t2, t1, 0.f, 0.f, nullptr);
        // zout = 0.25 * zin@t1
        gemm64ep_k<<<gp, 256>>>(0.25f, 0.f, zin, t1, zout, 0.f, 0.f, nullptr);
        float* tmp = zin; zin = zout; zout = tmp;
    }
    float* zfin = zin;

    // 7. a3 = softmax(scale * q_l @ k^T)  [h,256,8192]
    gemm128(true, MLAND, NTOK, DHEAD, qscale,
            ql, DHEAD, (long)MLAND * DHEAD,
            qkv + NHEADS * DHEAD, QKVW, DHEAD,
            a3, NTOK, (long)MLAND * NTOK, NHEADS);
    softmax8192_k<<<NHEADS * MLAND, 1024>>>(a3);

    // 8. a3v = a3 @ v  [h,256,64]  (split-K 32, atomic; pre-zeroed)
    {
        dim3 g(1, MLAND / 128, NHEADS * 32);
        gemm12864_k<<<g, 256>>>(MLAND, DHEAD, NTOK, 1.f,
                                a3, NTOK, (long)MLAND * NTOK,
                                qkv + 2 * NHEADS * DHEAD, QKVW, DHEAD,
                                a3v, DHEAD, (long)MLAND * DHEAD, 32);
    }

    // 9. w1 = a1 @ zfin  [h,8192,256]
    gemm128(false, NTOK, MLAND, MLAND, 1.f,
            a1, MLAND, (long)NTOK * MLAND, zfin, MLAND, smm,
            w1, MLAND, (long)NTOK * MLAND, NHEADS);

    // 10. xh[n, h*64:+64] = w1 @ a3v
    {
        dim3 g(1, NTOK / 128, NHEADS);
        gemm12864_k<<<g, 256>>>(NTOK, DHEAD, MLAND, 1.f,
                                w1, MLAND, (long)NTOK * MLAND,
                                a3v, DHEAD, (long)MLAND * DHEAD,
                                xh, DMODEL, DHEAD, 1);
    }

    // 11. residual depthwise conv on v, added into xh
    convadd_k<<<(int)(((long)NTOK * DMODEL + 255) / 256), 256>>>(qkv, rker, xh);

    // 12. xg = xh @ w_out^T ; enc = xg + b_out + dense
    gemm128(true, NTOK, DMODEL, DMODEL, 1.f, xh, DMODEL, 0, w_out, DMODEL, 0,
            xg, DMODEL, 0, 1);
    enc_k<<<(int)(((long)NTOK * DMODEL + 255) / 256), 256>>>(xg, b_out, dense, enc);

    // 13. qe = enc @ wq ; ke = enc @ wk
    gemm128(false, NTOK, WPD, DMODEL, 1.f, enc, DMODEL, 0, wq, WPD, 0, qe, WPD, 0, 1);
    gemm128(false, NTOK, WPD, DMODEL, 1.f, enc, DMODEL, 0, wk, WPD, 0, ke, WPD, 0, 1);

    // 14. edge scores -> segment sum (Araw pre-zeroed)
    edge_k<<<(NEDGE + 7) / 8, 256>>>(qe, ke, arows, acols, avals, Araw);

    // 15. alpha = softmax(A_raw) over all N
    softmax_all_k<<<1, 1024>>>(Araw, alpha, NTOK);

    // 16. value = dense @ wv_w^T
    gemm128(true, NTOK, DMODEL, DMODEL, 1.f, dense, DMODEL, 0, wv_w, DMODEL, 0,
            val, DMODEL, 0, 1);

    // 17. final gated blend + A_raw copy
    final_k<<<(int)(((long)NTOK * DMODEL + 255) / 256), 256>>>(val, wv_b, alpha, enc, Araw, out);
}